// round 4
// baseline (speedup 1.0000x reference)
#include <cuda_runtime.h>

#define ROWS 8
#define THREADS 1024
#define D 4096

typedef unsigned long long u64;

// H-folded, pre-scaled inner matrices: C[s][n] = (B[s][n] @ H64) / 64
__device__ float g_C[2 * 64 * 64 * 64];

__device__ __forceinline__ u64 pack2(float x) {
    u64 r; asm("mov.b64 %0,{%1,%1};" : "=l"(r) : "f"(x)); return r;
}
__device__ __forceinline__ void fma2(u64& d, u64 a, u64 b) {
    asm("fma.rn.f32x2 %0,%1,%2,%3;" : "=l"(d) : "l"(a), "l"(b), "l"(d));
}
// swizzle: logical (block n, col c) -> physical col. Includes n bit5 so the
// two 32-block halves land on disjoint bank halves for the FWHT pass.
__device__ __forceinline__ int swz(int n, int c) {
    return n * 64 + (c ^ ((((n & 7) ^ (((n >> 5) & 1) << 1))) << 3));
}

// ---------------- prepass: C = (B @ H64) / 64 ----------------
__global__ void prep_kernel(const float* __restrict__ innerB) {
    const int t = blockIdx.x * blockDim.x + threadIdx.x;   // row of a 64x64 block
    const float4* src = reinterpret_cast<const float4*>(innerB + (size_t)t * 64);
    float v[64];
    #pragma unroll
    for (int k = 0; k < 16; k++) {
        float4 f = src[k];
        v[4*k] = f.x; v[4*k+1] = f.y; v[4*k+2] = f.z; v[4*k+3] = f.w;
    }
    #pragma unroll
    for (int h = 1; h < 64; h <<= 1)
        #pragma unroll
        for (int m = 0; m < 64; m += 2*h)
            #pragma unroll
            for (int k = 0; k < h; k++) {
                float a = v[m+k], b = v[m+k+h];
                v[m+k] = a + b; v[m+k+h] = a - b;
            }
    float4* dst = reinterpret_cast<float4*>(g_C + (size_t)t * 64);
    const float s = 1.0f / 64.0f;
    #pragma unroll
    for (int k = 0; k < 16; k++)
        dst[k] = make_float4(v[4*k]*s, v[4*k+1]*s, v[4*k+2]*s, v[4*k+3]*s);
}

// ---------------- main fused kernel ----------------
__global__ __launch_bounds__(THREADS, 1)
void bh_fused_kernel(const float* __restrict__ x,
                     const float* __restrict__ finalB,
                     float* __restrict__ out)
{
    extern __shared__ float sd[];   // ROWS * D floats, swizzled layout
    const int tid = threadIdx.x;
    const size_t row0 = (size_t)blockIdx.x * ROWS;

    // ---- load ROWS rows (coalesced gmem read, swizzled smem store) ----
    {
        const float4* gx = reinterpret_cast<const float4*>(x + row0 * D);
        float4* s4 = reinterpret_cast<float4*>(sd);
        #pragma unroll
        for (int k = 0; k < (ROWS * D / 4) / THREADS; k++) {
            const int f   = tid + k * THREADS;        // global float4 idx in tile
            const int r   = f >> 10;                  // 1024 float4 per row
            const int cq  = f & 1023;
            const int n   = cq >> 4;                  // block
            const int c   = (cq & 15) * 4;            // col within block
            s4[r * 1024 + (swz(n, c) >> 2)] = gx[f];
        }
    }
    __syncthreads();

    // stage-matmul mapping: 16 threads per group, 4 output cols each
    const int g  = tid >> 4;         // group 0..63
    const int oc = (tid & 15) * 4;   // output-col base within group
    const int pb = swz(g, oc);       // physical col base for writes (16B-aligned)

    // FWHT mapping: warp w -> row hr=w>>2, col base (w&3)*16; lane: h2=l>>4, hj
    const int lane = tid & 31;
    const int w    = tid >> 5;
    const int hr   = w >> 2;
    const int hj   = ((w & 3) << 4) + (lane & 15);
    const int h2   = lane >> 4;              // which 32-block half
    const int mb   = h2 << 5;                // 0 or 32

    #pragma unroll 1
    for (int stage = 0; stage < 2; stage++) {
        // ---- block-diag 64x64 matmul with C (inner H64 + scale folded) ----
        const float* C = g_C + ((size_t)stage * 64 + g) * 64 * 64;

        u64 acc[ROWS][2];
        #pragma unroll
        for (int r = 0; r < ROWS; r++) { acc[r][0] = 0ull; acc[r][1] = 0ull; }

        #pragma unroll 4
        for (int j = 0; j < 64; j += 2) {
            const ulonglong2 c0 = *reinterpret_cast<const ulonglong2*>(&C[j * 64 + oc]);
            const ulonglong2 c1 = *reinterpret_cast<const ulonglong2*>(&C[(j + 1) * 64 + oc]);
            const int pj = swz(g, j);                 // j even -> float2-aligned
            #pragma unroll
            for (int r = 0; r < ROWS; r++) {
                const float2 xp = *reinterpret_cast<const float2*>(&sd[r * D + pj]);
                const u64 xs0 = pack2(xp.x);
                const u64 xs1 = pack2(xp.y);
                fma2(acc[r][0], xs0, c0.x);
                fma2(acc[r][1], xs0, c0.y);
                fma2(acc[r][0], xs1, c1.x);
                fma2(acc[r][1], xs1, c1.y);
            }
        }
        __syncthreads();   // all reads of the stage input done before overwrite
        #pragma unroll
        for (int r = 0; r < ROWS; r++)
            *reinterpret_cast<ulonglong2*>(&sd[r * D + pb]) =
                make_ulonglong2(acc[r][0], acc[r][1]);
        __syncthreads();

        // ---- outer H64: 5 levels in-register on a 32-half, top level via shfl ----
        {
            float v[32];
            #pragma unroll
            for (int m = 0; m < 32; m++)
                v[m] = sd[hr * D + swz(mb + m, hj)];
            #pragma unroll
            for (int h = 1; h < 32; h <<= 1)
                #pragma unroll
                for (int m0 = 0; m0 < 32; m0 += 2*h)
                    #pragma unroll
                    for (int k = 0; k < h; k++) {
                        float a = v[m0+k], b = v[m0+k+h];
                        v[m0+k] = a + b; v[m0+k+h] = a - b;
                    }
            // cross-half level h=32 via shfl.bfly with lane^16 (other half)
            #pragma unroll
            for (int m = 0; m < 32; m++) {
                const float p = __shfl_xor_sync(0xffffffffu, v[m], 16);
                v[m] = h2 ? (p - v[m]) : (v[m] + p);
            }
            #pragma unroll
            for (int m = 0; m < 32; m++)
                sd[hr * D + swz(mb + m, hj)] = v[m];
        }
        __syncthreads();
    }

    // ---------------- final block-diag 128 x (32x32) matmul -> GMEM ----------------
    {
        const int rect_lo = tid >> 4;      // 0..63 (16 threads per rect)
        const int oc2     = (tid & 15) * 2;

        #pragma unroll 1
        for (int pass = 0; pass < 2; pass++) {
            const int rect = pass * 64 + rect_lo;
            const int n    = rect >> 1;
            const int cb   = (rect & 1) * 32;
            const float* B = finalB + (size_t)rect * 32 * 32;

            u64 acc[ROWS];
            #pragma unroll
            for (int r = 0; r < ROWS; r++) acc[r] = 0ull;

            #pragma unroll 4
            for (int j = 0; j < 32; j += 2) {
                const u64 b0 = *reinterpret_cast<const u64*>(&B[j * 32 + oc2]);
                const u64 b1 = *reinterpret_cast<const u64*>(&B[(j + 1) * 32 + oc2]);
                const int pj = swz(n, cb + j);        // j even -> float2-aligned
                #pragma unroll
                for (int r = 0; r < ROWS; r++) {
                    const float2 xp = *reinterpret_cast<const float2*>(&sd[r * D + pj]);
                    fma2(acc[r], pack2(xp.x), b0);
                    fma2(acc[r], pack2(xp.y), b1);
                }
            }
            #pragma unroll
            for (int r = 0; r < ROWS; r++)
                *reinterpret_cast<u64*>(out + (row0 + r) * D + rect * 32 + oc2) = acc[r];
        }
    }
}

extern "C" void kernel_launch(void* const* d_in, const int* in_sizes, int n_in,
                              void* d_out, int out_size) {
    const float* x  = (const float*)d_in[0];   // [4,4096,4096] f32
    const float* iB = (const float*)d_in[1];   // [2,64,64,64]  f32
    const float* fB = (const float*)d_in[2];   // [128,32,32]   f32
    float* out = (float*)d_out;                // [4,4096,4096] f32

    prep_kernel<<<64, 128>>>(iB);

    const int smem = ROWS * D * sizeof(float); // 131072 bytes
    cudaFuncSetAttribute(bh_fused_kernel,
                         cudaFuncAttributeMaxDynamicSharedMemorySize, smem);
    const int nrows = 4 * 4096;
    bh_fused_kernel<<<nrows / ROWS, THREADS, smem>>>(x, fB, out);
}